// round 15
// baseline (speedup 1.0000x reference)
#include <cuda_runtime.h>
#include <cuda_bf16.h>
#include <cstdint>

// ---------------- problem constants ----------------
#define NPTS   5000
#define DF     128
#define HF     208
#define WFE    208
#define HWSZ   (HF*WFE)        // 43264
#define LCC    10816
#define TPATCH 5
#define INV_S  0.08838834764831845f   // 1/sqrt(128)

// ---------------- device scratch ----------------
__device__ float g_ctx0[2*DF];
__device__ float g_ctx1[2*DF];
__device__ float g_Wc[384*128];        // inv_s * corr_fuse_w @ M1
__device__ float g_Dc[256*128];        // down_proj_w @ M2
__device__ float g_biasc[128];
__device__ float g_Wtf[4*12*4096];     // [hb][panel 0..11] tf32 B panels in mma-frag layout
__device__ float g_base[2*NPTS*128];
__device__ int   g_glist[2*NPTS];
__device__ int   g_gcount[2];
// transposed features: (b, y, x, c) with c contiguous
__device__ float g_f0t[2*HWSZ*DF];
__device__ float g_f1t[2*HWSZ*DF];

__device__ __forceinline__ float to_tf32(float x) {
    unsigned u;
    asm("cvt.rna.tf32.f32 %0, %1;" : "=r"(u) : "f"(x));
    return __uint_as_float(u);
}

// ---------------- kernel 0 (fused): ctx means + weight folding ----------------
// blocks [0,512):    per-(b,c) spatial means (0..255 f0, 256..511 f1)
// blocks [512,1153): wcomb rows (512..895 Wc, 896..1151 Dc, 1152 bias+counters)
__global__ __launch_bounds__(256) void cw_kernel(
        const float* __restrict__ f0, const float* __restrict__ f1,
        const float* __restrict__ corr_w, const float* __restrict__ corr_b,
        const float* __restrict__ dp_w,   const float* __restrict__ dp_b,
        const float* __restrict__ mw,     const float* __restrict__ mb) {
    int bx = blockIdx.x;
    int tid = threadIdx.x;
    if (bx < 512) {
        const float* src = (bx < 256) ? f0 : f1;
        int bc = bx & 255;
        const float* p = src + (size_t)bc * HWSZ;
        float s = 0.f;
        for (int i = tid; i < HWSZ; i += 256) s += p[i];
        __shared__ float red[256];
        red[tid] = s;
        __syncthreads();
        for (int off = 128; off; off >>= 1) {
            if (tid < off) red[tid] += red[tid + off];
            __syncthreads();
        }
        if (tid == 0) {
            float m = red[0] * (1.0f / (float)HWSZ);
            if (bx < 256) g_ctx0[bc] = m; else g_ctx1[bc] = m;
        }
        return;
    }
    int r = bx - 512;
    __shared__ float row[128];
    __shared__ float row2[128];
    int c = tid;
    if (r < 384) {
        if (c < 128) row[c] = corr_w[r*128 + c];
        __syncthreads();
        if (c < 128) {
            float acc = 0.f;
            #pragma unroll 8
            for (int t = 0; t < 128; t++) acc += row[t] * mw[t*128 + c];
            g_Wc[r*128 + c] = acc * INV_S;
        }
    } else if (r < 640) {
        int rr = r - 384;
        if (c < 128) row[c] = dp_w[rr*128 + c];
        __syncthreads();
        if (c < 128) {
            float acc = 0.f;
            #pragma unroll 8
            for (int t = 0; t < 128; t++) acc += row[t] * mw[(128 + t)*128 + c];
            g_Dc[rr*128 + c] = acc;
        }
    } else {
        if (c < 128) { row[c] = corr_b[c]; row2[c] = dp_b[c]; }
        __syncthreads();
        if (c < 128) {
            float acc = mb[c];
            #pragma unroll 4
            for (int t = 0; t < 128; t++)
                acc += row[t] * mw[t*128 + c] + row2[t] * mw[(128 + t)*128 + c];
            g_biasc[c] = acc;
            if (c == 0) { g_gcount[0] = 0; g_gcount[1] = 0; }
        }
    }
}

// ---------------- kernel 1: feature transpose (b,c,y,x) -> (b,y,x,c) ----------------
__global__ __launch_bounds__(256) void tr_kernel(const float* __restrict__ f0,
                                                 const float* __restrict__ f1) {
    __shared__ float ts[32][33];
    int xb = blockIdx.x * 32;          // 7 x-blocks (last partial)
    int y  = blockIdx.y;
    int z  = blockIdx.z;               // src(2) x b(2) x cblk(4)
    int cb = (z & 3) * 32;
    int b  = (z >> 2) & 1;
    const float* f = (z >> 3) ? f1 : f0;
    float*       o = (z >> 3) ? g_f1t : g_f0t;
    int tx = threadIdx.x & 31, ty = threadIdx.x >> 5;   // ty 0..7
    #pragma unroll
    for (int i = 0; i < 4; i++) {
        int x = xb + tx, c = cb + ty + i*8;
        ts[ty + i*8][tx] = (x < WFE) ? __ldg(f + ((size_t)(b*DF + c)*HF + y)*WFE + x) : 0.f;
    }
    __syncthreads();
    #pragma unroll
    for (int i = 0; i < 4; i++) {
        int x = xb + ty + i*8, c = cb + tx;
        if (x < WFE)
            o[((size_t)(b*HF + y)*WFE + x)*DF + c] = ts[tx][ty + i*8];
    }
}

// ---------------- kernel 2 (fused prep): B panels + grouping + base GEMM ----------------
// blocks [0,48):   B panels (s*Wc on the fly -> tf32, mma-frag layout)
// blocks [48,68):  group points by b
// blocks [68,381): base = fc @ Dc + biasc
__global__ __launch_bounds__(256) void prep_kernel(
        const float* __restrict__ fc0, const float* __restrict__ fc1,
        const int* __restrict__ b_ids, const int* __restrict__ i_ids, const int* __restrict__ j_ids) {
    __shared__ float srcS[32*256];
    int bx = blockIdx.x;
    int tid = threadIdx.x;

    if (bx < 48) {
        int hb = bx / 12, pid = bx % 12;
        int h = hb >> 1, b = hb & 1;
        float* dst = g_Wtf + (size_t)bx * 4096;
        for (int e = tid; e < 4096; e += 256) {
            int n = e >> 5;            // 0..127
            int kloc = e & 31;         // 0..31
            int k = pid*32 + kloc;     // global k 0..383
            float s; int srcr;
            if (k < 128)      { s = 1.f;                     srcr = k; }
            else if (k < 256) { s = g_ctx1[b*128 + k - 128]; srcr = h ? (k + 128) : k; }
            else              { s = g_ctx0[b*128 + k - 256]; srcr = h ? (k - 128) : k; }
            float w = s * g_Wc[srcr*128 + n];
            int q = kloc >> 3, kk = kloc & 7;
            int ntile = n >> 3, g = n & 7;
            int lane = g*4 + (kk & 3);
            int reg  = kk >> 2;
            dst[((q*16 + ntile)*32 + lane)*2 + reg] = to_tf32(w);
        }
        return;
    }
    if (bx < 68) {
        int n = (bx - 48)*256 + tid;
        if (n < NPTS) {
            int g = b_ids[n];
            int p = atomicAdd(&g_gcount[g], 1);
            g_glist[g*NPTS + p] = n;
        }
        return;
    }
    int row0 = (bx - 68) * 32;
    for (int it = tid; it < 32*64; it += 256) {
        int rrow = it >> 6, ch = it & 63;
        int m = row0 + rrow;
        float4 v = make_float4(0.f, 0.f, 0.f, 0.f);
        if (m < 2*NPTS) {
            int half = (m >= NPTS);
            int n = m - half*NPTS;
            int b = b_ids[n];
            const float* src = half ? (fc1 + ((size_t)b*LCC + j_ids[n])*256)
                                    : (fc0 + ((size_t)b*LCC + i_ids[n])*256);
            v = __ldg((const float4*)src + ch);
        }
        *(float4*)(srcS + rrow*256 + ch*4) = v;
    }
    __syncthreads();
    int tx = tid & 31, ty = tid >> 5;
    float acc[4][4];
    #pragma unroll
    for (int r = 0; r < 4; r++)
        #pragma unroll
        for (int c = 0; c < 4; c++) acc[r][c] = g_biasc[tx*4 + c];
    for (int k = 0; k < 256; k++) {
        float4 w = __ldg((const float4*)(g_Dc + k*128) + tx);
        #pragma unroll
        for (int r = 0; r < 4; r++) {
            float a = srcS[(ty*4 + r)*256 + k];
            acc[r][0] += a*w.x; acc[r][1] += a*w.y; acc[r][2] += a*w.z; acc[r][3] += a*w.w;
        }
    }
    #pragma unroll
    for (int r = 0; r < 4; r++) {
        int m = row0 + ty*4 + r;
        if (m < 2*NPTS)
            *(float4*)(g_base + (size_t)m*128 + tx*4) =
                make_float4(acc[r][0], acc[r][1], acc[r][2], acc[r][3]);
    }
}

// ---------------- kernel 3: main gather + tf32 mma GEMM ----------------
// dynamic smem: A frag [0, 196608) ; B slot0 [196608, +16384) ; slot1 [212992, +16384)
#define SM_A_BYTES 196608
#define SM_B_OFF   196608
#define SMEM_BYTES 229376

// A fragment byte offset: [kstep(48)][mtile(8)][lane(32)][4 f32]
// m16n8k8 A frag: a0:(g, tig) a1:(g+8, tig) a2:(g, tig+4) a3:(g+8, tig+4)
__device__ __forceinline__ unsigned a_off(int row, int k) {   // k in 0..383
    int kstep = k >> 3, kk = k & 7;
    int mtile = row >> 4;
    int lane = (row & 7)*4 + (kk & 3);
    int reg  = ((kk >> 2) << 1) | ((row >> 3) & 1);
    return (unsigned)(((((kstep*8 + mtile)*32 + lane) << 2) + reg) << 2);
}
__device__ __forceinline__ void storeA(char* A, int row, int k, float v) {
    *(float*)(A + a_off(row, k)) = to_tf32(v);
}

__device__ __forceinline__ void mma_tf32(float* d, const uint4& a, const uint2& b) {
    asm volatile("mma.sync.aligned.m16n8k8.row.col.f32.tf32.tf32.f32 "
                 "{%0,%1,%2,%3}, {%4,%5,%6,%7}, {%8,%9}, {%0,%1,%2,%3};"
                 : "+f"(d[0]), "+f"(d[1]), "+f"(d[2]), "+f"(d[3])
                 : "r"(a.x), "r"(a.y), "r"(a.z), "r"(a.w), "r"(b.x), "r"(b.y));
}

__global__ __launch_bounds__(256, 1) void main_kernel(
        const int* __restrict__ i_ids, const int* __restrict__ j_ids,
        const int* __restrict__ w0c_p, const int* __restrict__ w1c_p,
        float* __restrict__ out) {
    extern __shared__ char smem[];
    int group = blockIdx.y;              // == b
    int cnt = g_gcount[group];
    int tile = blockIdx.x;
    if (tile*TPATCH >= cnt) return;

    int tid = threadIdx.x;
    int wid = tid >> 5;
    int lane = tid & 31;
    int wr = wid & 1, wc = wid >> 1;     // warp tile: m 64 x n 32
    int gl = lane >> 2, tig = lane & 3;  // fragment group / thread-in-group
    int w0c = *w0c_p, w1c = *w1c_p;
    char* Abase = smem;

    // ---- zero exactly the padded-row fragment words (rows 125..127) ----
    // Those are regs 1 and 3 of lanes 20..31 in mtile 7, every kstep.
    // Disjoint from all gather writes (rows <= 124), so no barrier needed here.
    for (int zi = tid; zi < 48*12; zi += 256) {
        int kstep = zi / 12, l = zi % 12;
        char* p = Abase + (((kstep*8 + 7)*32 + 20 + l) << 4);
        *(float*)(p + 4)  = 0.f;   // reg 1
        *(float*)(p + 12) = 0.f;   // reg 3
    }

    // ---- tile metadata ----
    int ns[TPATCH];
    int x0a[TPATCH], y0a[TPATCH], x1a[TPATCH], y1a[TPATCH];
    #pragma unroll
    for (int t = 0; t < TPATCH; t++) {
        int idx = tile*TPATCH + t;
        if (idx >= cnt) idx = cnt - 1;   // duplicate last -> identical redundant writes
        int n = g_glist[group*NPTS + idx];
        ns[t] = n;
        int ii = i_ids[n], jj = j_ids[n];
        int x0 = (ii % w0c)*2; if (x0 > WFE-1) x0 = WFE-1;
        int y0 = (ii / w0c)*2; if (y0 > HF -1) y0 = HF -1;
        int x1 = (jj % w1c)*2; if (x1 > WFE-1) x1 = WFE-1;
        int y1 = (jj / w1c)*2; if (y1 > HF -1) y1 = HF -1;
        x0a[t] = x0; y0a[t] = y0; x1a[t] = x1; y1a[t] = y1;
    }

    // ---- coalesced gather from transposed features ----
    // For each (t, wy): the 5x128 (wx, c) values are 640 contiguous floats.
    #pragma unroll 1
    for (int t = 0; t < TPATCH; t++) {
        #pragma unroll 1
        for (int wy = 0; wy < 5; wy++) {
            int y0 = y0a[t] + wy - 2;
            int y1 = y1a[t] + wy - 2;
            bool ok0 = ((unsigned)y0 < (unsigned)HF);
            bool ok1 = ((unsigned)y1 < (unsigned)HF);
            const float* s0 = g_f0t + ((size_t)(group*HF + (ok0 ? y0 : 0))*WFE + (x0a[t]-2))*DF;
            const float* s1 = g_f1t + ((size_t)(group*HF + (ok1 ? y1 : 0))*WFE + (x1a[t]-2))*DF;
            #pragma unroll 1
            for (int e = tid; e < 640; e += 256) {
                int wx = e >> 7, c = e & 127;
                bool vx0 = ok0 && ((unsigned)(x0a[t]-2+wx) < (unsigned)WFE);
                bool vx1 = ok1 && ((unsigned)(x1a[t]-2+wx) < (unsigned)WFE);
                float v0 = vx0 ? __ldg(s0 + e) : 0.f;
                float v1 = vx1 ? __ldg(s1 + e) : 0.f;
                int row = t*25 + wy*5 + wx;
                storeA(Abase, row, c,        v0*v1);   // cps -> k 0..127
                storeA(Abase, row, 128 + c,  v0);      // p0  -> k 128..255
                storeA(Abase, row, 256 + c,  v1);      // p1  -> k 256..383
            }
        }
    }
    __syncthreads();

    // ---- streamed B + MMA: 24 panels (2 halves x 12) ----
    float acc[4][4][4];
    #pragma unroll
    for (int i = 0; i < 4; i++)
        #pragma unroll
        for (int j = 0; j < 4; j++)
            #pragma unroll
            for (int q = 0; q < 4; q++) acc[i][j][q] = 0.f;

    uint4 pf[4];
    {
        const uint4* s0 = (const uint4*)(g_Wtf + (size_t)((0*2 + group)*12 + 0)*4096);
        #pragma unroll
        for (int i = 0; i < 4; i++) pf[i] = __ldg(s0 + i*256 + tid);
    }

    #pragma unroll 1
    for (int gp = 0; gp < 24; gp++) {
        int half = gp / 12, Pl = gp % 12;
        int slot = gp & 1;
        char* Bslot = smem + SM_B_OFF + slot*16384;

        __syncthreads();                                   // slot free (readers of gp-2 done)
        #pragma unroll
        for (int i = 0; i < 4; i++) ((uint4*)Bslot)[i*256 + tid] = pf[i];
        if (gp + 1 < 24) {
            int g2 = gp + 1, h2 = g2 / 12, P2 = g2 % 12;
            const uint4* s2 = (const uint4*)(g_Wtf + (size_t)((h2*2 + group)*12 + P2)*4096);
            #pragma unroll
            for (int i = 0; i < 4; i++) pf[i] = __ldg(s2 + i*256 + tid);
        }
        __syncthreads();                                   // slot filled

        #pragma unroll
        for (int q = 0; q < 4; q++) {
            int kstep = Pl*4 + q;                          // A k8-step 0..47
            uint4 ua[4];
            #pragma unroll
            for (int mtl = 0; mtl < 4; mtl++)
                ua[mtl] = *(const uint4*)(Abase + (((kstep*8 + (wr*4 + mtl))*32 + lane) << 4));
            uint2 ub[4];
            #pragma unroll
            for (int ntl = 0; ntl < 4; ntl++)
                ub[ntl] = *(const uint2*)(Bslot + (((q*16 + (wc*4 + ntl))*32 + lane) << 3));
            #pragma unroll
            for (int mtl = 0; mtl < 4; mtl++)
                #pragma unroll
                for (int ntl = 0; ntl < 4; ntl++)
                    mma_tf32(acc[mtl][ntl], ua[mtl], ub[ntl]);
        }

        // ---- end of a half: write out + reset acc ----
        if (Pl == 11) {
            #pragma unroll
            for (int mtl = 0; mtl < 4; mtl++) {
                #pragma unroll
                for (int rr = 0; rr < 2; rr++) {
                    int row = wr*64 + mtl*16 + gl + rr*8;
                    if (row < TPATCH*25) {
                        int t = row / 25, pos = row % 25;
                        size_t mrow = (size_t)half*NPTS + ns[t];
                        const float* bp = g_base + mrow*128;
                        float* op = out + (mrow*25 + pos)*128;
                        #pragma unroll
                        for (int ntl = 0; ntl < 4; ntl++) {
                            int col = wc*32 + ntl*8 + tig*2;
                            float2 b = *(const float2*)(bp + col);
                            float2 v;
                            v.x = acc[mtl][ntl][rr*2 + 0] + b.x;
                            v.y = acc[mtl][ntl][rr*2 + 1] + b.y;
                            *(float2*)(op + col) = v;
                        }
                    }
                }
            }
            #pragma unroll
            for (int i = 0; i < 4; i++)
                #pragma unroll
                for (int j = 0; j < 4; j++)
                    #pragma unroll
                    for (int q = 0; q < 4; q++) acc[i][j][q] = 0.f;
        }
    }
}

// ---------------- launch ----------------
extern "C" void kernel_launch(void* const* d_in, const int* in_sizes, int n_in,
                              void* d_out, int out_size) {
    const float* f0     = (const float*)d_in[0];
    const float* f1     = (const float*)d_in[1];
    const float* fc0    = (const float*)d_in[2];
    const float* fc1    = (const float*)d_in[3];
    const float* corr_w = (const float*)d_in[4];
    const float* corr_b = (const float*)d_in[5];
    const float* dp_w   = (const float*)d_in[6];
    const float* dp_b   = (const float*)d_in[7];
    const float* mw     = (const float*)d_in[8];
    const float* mb     = (const float*)d_in[9];
    const int* b_ids    = (const int*)d_in[10];
    const int* i_ids    = (const int*)d_in[11];
    const int* j_ids    = (const int*)d_in[12];
    const int* w0c      = (const int*)d_in[13];
    const int* w1c      = (const int*)d_in[14];
    float* out          = (float*)d_out;

    (void)in_sizes; (void)n_in; (void)out_size;

    cudaFuncSetAttribute(main_kernel, cudaFuncAttributeMaxDynamicSharedMemorySize, SMEM_BYTES);

    cw_kernel  <<<1153, 256>>>(f0, f1, corr_w, corr_b, dp_w, dp_b, mw, mb);  // launch 0
    tr_kernel  <<<dim3(7, 208, 16), 256>>>(f0, f1);                          // launch 1
    prep_kernel<<<381, 256>>>(fc0, fc1, b_ids, i_ids, j_ids);                // launch 2
    main_kernel<<<dim3((NPTS + TPATCH - 1)/TPATCH, 2), 256, SMEM_BYTES>>>(
        i_ids, j_ids, w0c, w1c, out);                                        // launch 3 -> ncu
}

// round 16
// speedup vs baseline: 1.0810x; 1.0810x over previous
#include <cuda_runtime.h>
#include <cuda_bf16.h>
#include <cstdint>

// ---------------- problem constants ----------------
#define NPTS   5000
#define DF     128
#define HF     208
#define WFE    208
#define HWSZ   (HF*WFE)        // 43264
#define LCC    10816
#define TPATCH 5
#define INV_S  0.08838834764831845f   // 1/sqrt(128)

// ---------------- device scratch ----------------
__device__ float g_ctx0[2*DF];
__device__ float g_ctx1[2*DF];
__device__ float g_Wc[384*128];        // inv_s * corr_fuse_w @ M1
__device__ float g_Dc[256*128];        // down_proj_w @ M2
__device__ float g_biasc[128];
__device__ float g_Wtf[4*12*4096];     // [hb][panel 0..11] tf32 B panels in mma-frag layout
__device__ float g_base[2*NPTS*128];
__device__ int   g_glist[2*NPTS];
__device__ int   g_gcount[2];

__device__ __forceinline__ float to_tf32(float x) {
    unsigned u;
    asm("cvt.rna.tf32.f32 %0, %1;" : "=r"(u) : "f"(x));
    return __uint_as_float(u);
}

// ---------------- kernel 1: per-(b,c) spatial means ----------------
__global__ void ctx_kernel(const float* __restrict__ f0, const float* __restrict__ f1) {
    int id = blockIdx.x;
    const float* src = (id < 256) ? f0 : f1;
    int bc = id & 255;
    const float* p = src + (size_t)bc * HWSZ;
    float s = 0.f;
    for (int i = threadIdx.x; i < HWSZ; i += 256) s += p[i];
    __shared__ float red[256];
    red[threadIdx.x] = s;
    __syncthreads();
    for (int off = 128; off; off >>= 1) {
        if (threadIdx.x < off) red[threadIdx.x] += red[threadIdx.x + off];
        __syncthreads();
    }
    if (threadIdx.x == 0) {
        float m = red[0] * (1.0f / (float)HWSZ);
        if (id < 256) g_ctx0[bc] = m; else g_ctx1[bc] = m;
    }
}

// ---------------- kernel 2: fold merge weights ----------------
__global__ void wcomb_kernel(const float* __restrict__ corr_w, const float* __restrict__ corr_b,
                             const float* __restrict__ dp_w,   const float* __restrict__ dp_b,
                             const float* __restrict__ mw,     const float* __restrict__ mb) {
    __shared__ float row[128];
    __shared__ float row2[128];
    int r = blockIdx.x;
    int c = threadIdx.x;
    if (r < 384) {
        row[c] = corr_w[r*128 + c];
        __syncthreads();
        float acc = 0.f;
        #pragma unroll 8
        for (int t = 0; t < 128; t++) acc += row[t] * mw[t*128 + c];
        g_Wc[r*128 + c] = acc * INV_S;
    } else if (r < 640) {
        int rr = r - 384;
        row[c] = dp_w[rr*128 + c];
        __syncthreads();
        float acc = 0.f;
        #pragma unroll 8
        for (int t = 0; t < 128; t++) acc += row[t] * mw[(128 + t)*128 + c];
        g_Dc[rr*128 + c] = acc;
    } else {
        row[c]  = corr_b[c];
        row2[c] = dp_b[c];
        __syncthreads();
        float acc = mb[c];
        #pragma unroll 4
        for (int t = 0; t < 128; t++)
            acc += row[t] * mw[t*128 + c] + row2[t] * mw[(128 + t)*128 + c];
        g_biasc[c] = acc;
        if (c == 0) { g_gcount[0] = 0; g_gcount[1] = 0; }
    }
}

// ---------------- fused prep kernel ----------------
// blocks [0,48):   B panels (s*Wc on the fly -> tf32, mma-frag layout)
// blocks [48,68):  group points by b
// blocks [68,381): base = fc @ Dc + biasc
// B panel layout (16KB = 4096 f32): [q(4 k8-steps)][ntile(16)][lane(32)][2 regs]
// m16n8k8 B frag: b0:(k=tig, n=g) b1:(k=tig+4, n=g); lane = g*4 + tig
__global__ __launch_bounds__(256) void prep_kernel(
        const float* __restrict__ fc0, const float* __restrict__ fc1,
        const int* __restrict__ b_ids, const int* __restrict__ i_ids, const int* __restrict__ j_ids) {
    __shared__ float srcS[32*256];     // used by base part only
    int bx = blockIdx.x;
    int tid = threadIdx.x;

    if (bx < 48) {                     // ---- B panel build ----
        int hb = bx / 12, pid = bx % 12;
        int h = hb >> 1, b = hb & 1;
        float* dst = g_Wtf + (size_t)bx * 4096;
        for (int e = tid; e < 4096; e += 256) {
            int n = e >> 5;            // 0..127
            int kloc = e & 31;         // 0..31
            int k = pid*32 + kloc;     // global k 0..383
            float s; int srcr;
            if (k < 128)      { s = 1.f;                     srcr = k; }
            else if (k < 256) { s = g_ctx1[b*128 + k - 128]; srcr = h ? (k + 128) : k; }
            else              { s = g_ctx0[b*128 + k - 256]; srcr = h ? (k - 128) : k; }
            float w = s * g_Wc[srcr*128 + n];
            int q = kloc >> 3, kk = kloc & 7;
            int ntile = n >> 3, g = n & 7;
            int lane = g*4 + (kk & 3);
            int reg  = kk >> 2;
            dst[((q*16 + ntile)*32 + lane)*2 + reg] = to_tf32(w);
        }
        return;
    }
    if (bx < 68) {                     // ---- grouping ----
        int n = (bx - 48)*256 + tid;
        if (n < NPTS) {
            int g = b_ids[n];
            int p = atomicAdd(&g_gcount[g], 1);
            g_glist[g*NPTS + p] = n;
        }
        return;
    }
    // ---- base GEMM: rows [row0, row0+32) of 2N x 128 ----
    int row0 = (bx - 68) * 32;
    for (int it = tid; it < 32*64; it += 256) {
        int rrow = it >> 6, ch = it & 63;
        int m = row0 + rrow;
        float4 v = make_float4(0.f, 0.f, 0.f, 0.f);
        if (m < 2*NPTS) {
            int half = (m >= NPTS);
            int n = m - half*NPTS;
            int b = b_ids[n];
            const float* src = half ? (fc1 + ((size_t)b*LCC + j_ids[n])*256)
                                    : (fc0 + ((size_t)b*LCC + i_ids[n])*256);
            v = __ldg((const float4*)src + ch);
        }
        *(float4*)(srcS + rrow*256 + ch*4) = v;
    }
    __syncthreads();
    int tx = tid & 31, ty = tid >> 5;
    float acc[4][4];
    #pragma unroll
    for (int r = 0; r < 4; r++)
        #pragma unroll
        for (int c = 0; c < 4; c++) acc[r][c] = g_biasc[tx*4 + c];
    for (int k = 0; k < 256; k++) {
        float4 w = __ldg((const float4*)(g_Dc + k*128) + tx);
        #pragma unroll
        for (int r = 0; r < 4; r++) {
            float a = srcS[(ty*4 + r)*256 + k];
            acc[r][0] += a*w.x; acc[r][1] += a*w.y; acc[r][2] += a*w.z; acc[r][3] += a*w.w;
        }
    }
    #pragma unroll
    for (int r = 0; r < 4; r++) {
        int m = row0 + ty*4 + r;
        if (m < 2*NPTS)
            *(float4*)(g_base + (size_t)m*128 + tx*4) =
                make_float4(acc[r][0], acc[r][1], acc[r][2], acc[r][3]);
    }
}

// ---------------- main: gather + tf32 mma GEMM, 512 threads ----------------
// dynamic smem: A frag [0, 196608) ; B slot0 [196608, +16384) ; slot1 [212992, +16384)
#define SM_A_BYTES 196608
#define SM_B_OFF   196608
#define SMEM_BYTES 229376

// A fragment byte offset: [kstep(48)][mtile(8)][lane(32)][4 f32]
// m16n8k8 A frag: a0:(g, tig) a1:(g+8, tig) a2:(g, tig+4) a3:(g+8, tig+4)
__device__ __forceinline__ unsigned a_off(int row, int k) {   // k in 0..383
    int kstep = k >> 3, kk = k & 7;
    int mtile = row >> 4;
    int lane = (row & 7)*4 + (kk & 3);
    int reg  = ((kk >> 2) << 1) | ((row >> 3) & 1);
    return (unsigned)(((((kstep*8 + mtile)*32 + lane) << 2) + reg) << 2);
}
__device__ __forceinline__ void storeA(char* A, int row, int k, float v) {
    *(float*)(A + a_off(row, k)) = to_tf32(v);
}

__device__ __forceinline__ void mma_tf32(float* d, const uint4& a, const uint2& b) {
    asm volatile("mma.sync.aligned.m16n8k8.row.col.f32.tf32.tf32.f32 "
                 "{%0,%1,%2,%3}, {%4,%5,%6,%7}, {%8,%9}, {%0,%1,%2,%3};"
                 : "+f"(d[0]), "+f"(d[1]), "+f"(d[2]), "+f"(d[3])
                 : "r"(a.x), "r"(a.y), "r"(a.z), "r"(a.w), "r"(b.x), "r"(b.y));
}

__global__ __launch_bounds__(512, 1) void main_kernel(
        const float* __restrict__ f0, const float* __restrict__ f1,
        const int* __restrict__ i_ids, const int* __restrict__ j_ids,
        const int* __restrict__ w0c_p, const int* __restrict__ w1c_p,
        float* __restrict__ out) {
    extern __shared__ char smem[];
    int group = blockIdx.y;              // == b
    int cnt = g_gcount[group];
    int tile = blockIdx.x;
    if (tile*TPATCH >= cnt) return;

    int tid = threadIdx.x;
    int wid = tid >> 5;
    int lane = tid & 31;
    int wr = wid & 3, wc = wid >> 2;     // warp tile: m 32 x n 32 (16 warps)
    int gl = lane >> 2, tig = lane & 3;  // fragment group / thread-in-group
    int w0c = *w0c_p, w1c = *w1c_p;
    char* Abase = smem;

    // ---- zero exactly the padded-row fragment words (rows 125..127) ----
    // regs 1 and 3 of lanes 20..31 in mtile 7, every kstep. Disjoint from
    // gather writes (rows <= 124); covered by the post-gather barrier.
    for (int zi = tid; zi < 48*12; zi += 512) {
        int kstep = zi / 12, l = zi % 12;
        char* p = Abase + (((kstep*8 + 7)*32 + 20 + l) << 4);
        *(float*)(p + 4)  = 0.f;   // reg 1
        *(float*)(p + 12) = 0.f;   // reg 3
    }

    // ---- tile metadata ----
    int ns[TPATCH];
    int x0a[TPATCH], y0a[TPATCH], x1a[TPATCH], y1a[TPATCH];
    #pragma unroll
    for (int t = 0; t < TPATCH; t++) {
        int idx = tile*TPATCH + t;
        if (idx >= cnt) idx = cnt - 1;   // duplicate last -> identical redundant writes
        int n = g_glist[group*NPTS + idx];
        ns[t] = n;
        int ii = i_ids[n], jj = j_ids[n];
        int x0 = (ii % w0c)*2; if (x0 > WFE-1) x0 = WFE-1;
        int y0 = (ii / w0c)*2; if (y0 > HF -1) y0 = HF -1;
        int x1 = (jj % w1c)*2; if (x1 > WFE-1) x1 = WFE-1;
        int y1 = (jj / w1c)*2; if (y1 > HF -1) y1 = HF -1;
        x0a[t] = x0; y0a[t] = y0; x1a[t] = x1; y1a[t] = y1;
    }

    // ---- gather patches (direct layout), tf32 round, into fragment A ----
    #pragma unroll
    for (int t = 0; t < TPATCH; t++) {
        for (int item = tid; item < 640; item += 512) {    // item = c*5 + wy
            int wy = item % 5;
            int c  = item / 5;
            float v0[5], v1[5];
            {
                int y = y0a[t] + wy - 2;
                bool yok = ((unsigned)y < (unsigned)HF);
                const float* src = f0 + ((size_t)(group*DF + c)*HF + (yok ? y : 0))*WFE;
                #pragma unroll
                for (int wx = 0; wx < 5; wx++) {
                    int x = x0a[t] + wx - 2;
                    v0[wx] = (yok && (unsigned)x < (unsigned)WFE) ? __ldg(src + x) : 0.f;
                }
            }
            {
                int y = y1a[t] + wy - 2;
                bool yok = ((unsigned)y < (unsigned)HF);
                const float* src = f1 + ((size_t)(group*DF + c)*HF + (yok ? y : 0))*WFE;
                #pragma unroll
                for (int wx = 0; wx < 5; wx++) {
                    int x = x1a[t] + wx - 2;
                    v1[wx] = (yok && (unsigned)x < (unsigned)WFE) ? __ldg(src + x) : 0.f;
                }
            }
            #pragma unroll
            for (int wx = 0; wx < 5; wx++) {
                int row = t*25 + wy*5 + wx;
                storeA(Abase, row, c,        v0[wx]*v1[wx]);   // cps -> k 0..127
                storeA(Abase, row, 128 + c,  v0[wx]);          // p0  -> k 128..255
                storeA(Abase, row, 256 + c,  v1[wx]);          // p1  -> k 256..383
            }
        }
    }
    __syncthreads();

    // ---- streamed B + MMA: 24 panels, ONE sync per panel ----
    float acc[2][4][4];
    #pragma unroll
    for (int i = 0; i < 2; i++)
        #pragma unroll
        for (int j = 0; j < 4; j++)
            #pragma unroll
            for (int q = 0; q < 4; q++) acc[i][j][q] = 0.f;

    uint4 pf[2];
    {
        const uint4* s0 = (const uint4*)(g_Wtf + (size_t)((0*2 + group)*12 + 0)*4096);
        #pragma unroll
        for (int i = 0; i < 2; i++) pf[i] = __ldg(s0 + i*512 + tid);
    }

    #pragma unroll 1
    for (int gp = 0; gp < 24; gp++) {
        int half = gp / 12, Pl = gp % 12;
        char* Bslot = smem + SM_B_OFF + (gp & 1)*16384;

        // store this panel, then prefetch next, then one sync.
        // Safe vs readers of this slot from iteration gp-2: they passed
        // sync(gp-1) after their reads; our store is after sync(gp-1) too.
        #pragma unroll
        for (int i = 0; i < 2; i++) ((uint4*)Bslot)[i*512 + tid] = pf[i];
        if (gp + 1 < 24) {
            int g2 = gp + 1, h2 = g2 / 12, P2 = g2 % 12;
            const uint4* s2 = (const uint4*)(g_Wtf + (size_t)((h2*2 + group)*12 + P2)*4096);
            #pragma unroll
            for (int i = 0; i < 2; i++) pf[i] = __ldg(s2 + i*512 + tid);
        }
        __syncthreads();

        #pragma unroll
        for (int q = 0; q < 4; q++) {
            int kstep = Pl*4 + q;                          // A k8-step 0..47
            uint4 ua[2];
            #pragma unroll
            for (int mtl = 0; mtl < 2; mtl++)
                ua[mtl] = *(const uint4*)(Abase + (((kstep*8 + (wr*2 + mtl))*32 + lane) << 4));
            uint2 ub[4];
            #pragma unroll
            for (int ntl = 0; ntl < 4; ntl++)
                ub[ntl] = *(const uint2*)(Bslot + (((q*16 + (wc*4 + ntl))*32 + lane) << 3));
            #pragma unroll
            for (int mtl = 0; mtl < 2; mtl++)
                #pragma unroll
                for (int ntl = 0; ntl < 4; ntl++)
                    mma_tf32(acc[mtl][ntl], ua[mtl], ub[ntl]);
        }

        // ---- end of a half: write out + reset acc ----
        if (Pl == 11) {
            #pragma unroll
            for (int mtl = 0; mtl < 2; mtl++) {
                #pragma unroll
                for (int rr = 0; rr < 2; rr++) {
                    int row = wr*32 + mtl*16 + gl + rr*8;
                    if (row < TPATCH*25) {
                        int t = row / 25, pos = row % 25;
                        size_t mrow = (size_t)half*NPTS + ns[t];
                        const float* bp = g_base + mrow*128;
                        float* op = out + (mrow*25 + pos)*128;
                        #pragma unroll
                        for (int ntl = 0; ntl < 4; ntl++) {
                            int col = wc*32 + ntl*8 + tig*2;
                            float2 b = *(const float2*)(bp + col);
                            float2 v;
                            v.x = acc[mtl][ntl][rr*2 + 0] + b.x;
                            v.y = acc[mtl][ntl][rr*2 + 1] + b.y;
                            *(float2*)(op + col) = v;
                        }
                    }
                }
            }
            #pragma unroll
            for (int i = 0; i < 2; i++)
                #pragma unroll
                for (int j = 0; j < 4; j++)
                    #pragma unroll
                    for (int q = 0; q < 4; q++) acc[i][j][q] = 0.f;
        }
    }
}

// ---------------- launch ----------------
extern "C" void kernel_launch(void* const* d_in, const int* in_sizes, int n_in,
                              void* d_out, int out_size) {
    const float* f0     = (const float*)d_in[0];
    const float* f1     = (const float*)d_in[1];
    const float* fc0    = (const float*)d_in[2];
    const float* fc1    = (const float*)d_in[3];
    const float* corr_w = (const float*)d_in[4];
    const float* corr_b = (const float*)d_in[5];
    const float* dp_w   = (const float*)d_in[6];
    const float* dp_b   = (const float*)d_in[7];
    const float* mw     = (const float*)d_in[8];
    const float* mb     = (const float*)d_in[9];
    const int* b_ids    = (const int*)d_in[10];
    const int* i_ids    = (const int*)d_in[11];
    const int* j_ids    = (const int*)d_in[12];
    const int* w0c      = (const int*)d_in[13];
    const int* w1c      = (const int*)d_in[14];
    float* out          = (float*)d_out;

    (void)in_sizes; (void)n_in; (void)out_size;

    cudaFuncSetAttribute(main_kernel, cudaFuncAttributeMaxDynamicSharedMemorySize, SMEM_BYTES);

    ctx_kernel  <<<512, 256>>>(f0, f1);                                      // launch 0
    wcomb_kernel<<<641, 128>>>(corr_w, corr_b, dp_w, dp_b, mw, mb);          // launch 1
    prep_kernel <<<381, 256>>>(fc0, fc1, b_ids, i_ids, j_ids);               // launch 2
    main_kernel <<<dim3((NPTS + TPATCH - 1)/TPATCH, 2), 512, SMEM_BYTES>>>(
        f0, f1, i_ids, j_ids, w0c, w1c, out);                                // launch 3 -> ncu
}

// round 17
// speedup vs baseline: 1.1092x; 1.0261x over previous
#include <cuda_runtime.h>
#include <cuda_bf16.h>
#include <cstdint>

// ---------------- problem constants ----------------
#define NPTS   5000
#define DF     128
#define HF     208
#define WFE    208
#define HWSZ   (HF*WFE)        // 43264
#define LCC    10816
#define TPATCH 2
#define INV_S  0.08838834764831845f   // 1/sqrt(128)

// ---------------- device scratch ----------------
__device__ float g_ctx0[2*DF];
__device__ float g_ctx1[2*DF];
__device__ float g_Wc[384*128];        // inv_s * corr_fuse_w @ M1
__device__ float g_Dc[256*128];        // down_proj_w @ M2
__device__ float g_biasc[128];
__device__ float g_Wtf[4*12*4096];     // [hb][stored panel 0..11] tf32 B in mma-frag layout
__device__ float g_base[2*NPTS*128];
__device__ int   g_glist[2*NPTS];
__device__ int   g_gcount[2];

__device__ __forceinline__ float to_tf32(float x) {
    unsigned u;
    asm("cvt.rna.tf32.f32 %0, %1;" : "=r"(u) : "f"(x));
    return __uint_as_float(u);
}

// ---------------- kernel 1: per-(b,c) spatial means ----------------
__global__ void ctx_kernel(const float* __restrict__ f0, const float* __restrict__ f1) {
    int id = blockIdx.x;
    const float* src = (id < 256) ? f0 : f1;
    int bc = id & 255;
    const float* p = src + (size_t)bc * HWSZ;
    float s = 0.f;
    for (int i = threadIdx.x; i < HWSZ; i += 256) s += p[i];
    __shared__ float red[256];
    red[threadIdx.x] = s;
    __syncthreads();
    for (int off = 128; off; off >>= 1) {
        if (threadIdx.x < off) red[threadIdx.x] += red[threadIdx.x + off];
        __syncthreads();
    }
    if (threadIdx.x == 0) {
        float m = red[0] * (1.0f / (float)HWSZ);
        if (id < 256) g_ctx0[bc] = m; else g_ctx1[bc] = m;
    }
}

// ---------------- kernel 2: fold merge weights ----------------
__global__ void wcomb_kernel(const float* __restrict__ corr_w, const float* __restrict__ corr_b,
                             const float* __restrict__ dp_w,   const float* __restrict__ dp_b,
                             const float* __restrict__ mw,     const float* __restrict__ mb) {
    __shared__ float row[128];
    __shared__ float row2[128];
    int r = blockIdx.x;
    int c = threadIdx.x;
    if (r < 384) {
        row[c] = corr_w[r*128 + c];
        __syncthreads();
        float acc = 0.f;
        #pragma unroll 8
        for (int t = 0; t < 128; t++) acc += row[t] * mw[t*128 + c];
        g_Wc[r*128 + c] = acc * INV_S;
    } else if (r < 640) {
        int rr = r - 384;
        row[c] = dp_w[rr*128 + c];
        __syncthreads();
        float acc = 0.f;
        #pragma unroll 8
        for (int t = 0; t < 128; t++) acc += row[t] * mw[(128 + t)*128 + c];
        g_Dc[rr*128 + c] = acc;
    } else {
        row[c]  = corr_b[c];
        row2[c] = dp_b[c];
        __syncthreads();
        float acc = mb[c];
        #pragma unroll 4
        for (int t = 0; t < 128; t++)
            acc += row[t] * mw[t*128 + c] + row2[t] * mw[(128 + t)*128 + c];
        g_biasc[c] = acc;
        if (c == 0) { g_gcount[0] = 0; g_gcount[1] = 0; }
    }
}

// ---------------- fused prep kernel (unchanged layout) ----------------
// blocks [0,48):   B panels (s*Wc -> tf32, mma-frag layout)
// blocks [48,68):  group points by b
// blocks [68,381): base = fc @ Dc + biasc
// Stored panel (16KB = 4096 f32): [q(4 k8-steps)][ntile(16)][lane(32)][2 regs]
__global__ __launch_bounds__(256) void prep_kernel(
        const float* __restrict__ fc0, const float* __restrict__ fc1,
        const int* __restrict__ b_ids, const int* __restrict__ i_ids, const int* __restrict__ j_ids) {
    __shared__ float srcS[32*256];
    int bx = blockIdx.x;
    int tid = threadIdx.x;

    if (bx < 48) {
        int hb = bx / 12, pid = bx % 12;
        int h = hb >> 1, b = hb & 1;
        float* dst = g_Wtf + (size_t)bx * 4096;
        for (int e = tid; e < 4096; e += 256) {
            int n = e >> 5;
            int kloc = e & 31;
            int k = pid*32 + kloc;
            float s; int srcr;
            if (k < 128)      { s = 1.f;                     srcr = k; }
            else if (k < 256) { s = g_ctx1[b*128 + k - 128]; srcr = h ? (k + 128) : k; }
            else              { s = g_ctx0[b*128 + k - 256]; srcr = h ? (k - 128) : k; }
            float w = s * g_Wc[srcr*128 + n];
            int q = kloc >> 3, kk = kloc & 7;
            int ntile = n >> 3, g = n & 7;
            int lane = g*4 + (kk & 3);
            int reg  = kk >> 2;
            dst[((q*16 + ntile)*32 + lane)*2 + reg] = to_tf32(w);
        }
        return;
    }
    if (bx < 68) {
        int n = (bx - 48)*256 + tid;
        if (n < NPTS) {
            int g = b_ids[n];
            int p = atomicAdd(&g_gcount[g], 1);
            g_glist[g*NPTS + p] = n;
        }
        return;
    }
    int row0 = (bx - 68) * 32;
    for (int it = tid; it < 32*64; it += 256) {
        int rrow = it >> 6, ch = it & 63;
        int m = row0 + rrow;
        float4 v = make_float4(0.f, 0.f, 0.f, 0.f);
        if (m < 2*NPTS) {
            int half = (m >= NPTS);
            int n = m - half*NPTS;
            int b = b_ids[n];
            const float* src = half ? (fc1 + ((size_t)b*LCC + j_ids[n])*256)
                                    : (fc0 + ((size_t)b*LCC + i_ids[n])*256);
            v = __ldg((const float4*)src + ch);
        }
        *(float4*)(srcS + rrow*256 + ch*4) = v;
    }
    __syncthreads();
    int tx = tid & 31, ty = tid >> 5;
    float acc[4][4];
    #pragma unroll
    for (int r = 0; r < 4; r++)
        #pragma unroll
        for (int c = 0; c < 4; c++) acc[r][c] = g_biasc[tx*4 + c];
    for (int k = 0; k < 256; k++) {
        float4 w = __ldg((const float4*)(g_Dc + k*128) + tx);
        #pragma unroll
        for (int r = 0; r < 4; r++) {
            float a = srcS[(ty*4 + r)*256 + k];
            acc[r][0] += a*w.x; acc[r][1] += a*w.y; acc[r][2] += a*w.z; acc[r][3] += a*w.w;
        }
    }
    #pragma unroll
    for (int r = 0; r < 4; r++) {
        int m = row0 + ty*4 + r;
        if (m < 2*NPTS)
            *(float4*)(g_base + (size_t)m*128 + tx*4) =
                make_float4(acc[r][0], acc[r][1], acc[r][2], acc[r][3]);
    }
}

// ---------------- main: M=64 tile, 2 CTAs/SM ----------------
// dynamic smem: A frag [0, 98304) ; B slot0 [98304, +8192) ; slot1 [106496, +8192)
#define SM_A_BYTES 98304
#define SM_B_OFF   98304
#define SMEM_BYTES 114688

// A fragment byte offset: [kstep(48)][mtile(4)][lane(32)][4 f32]
// m16n8k8 A frag: a0:(g, tig) a1:(g+8, tig) a2:(g, tig+4) a3:(g+8, tig+4)
__device__ __forceinline__ unsigned a_off(int row, int k) {   // row 0..63, k 0..383
    int kstep = k >> 3, kk = k & 7;
    int mtile = row >> 4;
    int lane = (row & 7)*4 + (kk & 3);
    int reg  = ((kk >> 2) << 1) | ((row >> 3) & 1);
    return (unsigned)(((((kstep*4 + mtile)*32 + lane) << 2) + reg) << 2);
}
__device__ __forceinline__ void storeA(char* A, int row, int k, float v) {
    *(float*)(A + a_off(row, k)) = to_tf32(v);
}

__device__ __forceinline__ void mma_tf32(float* d, const uint4& a, const uint2& b) {
    asm volatile("mma.sync.aligned.m16n8k8.row.col.f32.tf32.tf32.f32 "
                 "{%0,%1,%2,%3}, {%4,%5,%6,%7}, {%8,%9}, {%0,%1,%2,%3};"
                 : "+f"(d[0]), "+f"(d[1]), "+f"(d[2]), "+f"(d[3])
                 : "r"(a.x), "r"(a.y), "r"(a.z), "r"(a.w), "r"(b.x), "r"(b.y));
}

__global__ __launch_bounds__(256, 2) void main_kernel(
        const float* __restrict__ f0, const float* __restrict__ f1,
        const int* __restrict__ i_ids, const int* __restrict__ j_ids,
        const int* __restrict__ w0c_p, const int* __restrict__ w1c_p,
        float* __restrict__ out) {
    extern __shared__ char smem[];
    int group = blockIdx.y;              // == b
    int cnt = g_gcount[group];
    int tile = blockIdx.x;
    if (tile*TPATCH >= cnt) return;

    int tid = threadIdx.x;
    int wid = tid >> 5;
    int lane = tid & 31;
    int wr = wid & 1, wc = wid >> 1;     // warp tile: m 32 x n 32 (8 warps: 2x4)
    int gl = lane >> 2, tig = lane & 3;
    int w0c = *w0c_p, w1c = *w1c_p;
    char* Abase = smem;

    // ---- zero mtile 3 slab (covers padded rows 50..63; rows 48,49 re-written
    //      by the gather after the barrier) ----
    for (int zi = tid; zi < 48*32; zi += 256) {
        int kstep = zi >> 5, l = zi & 31;
        *(uint4*)(Abase + (((kstep*4 + 3)*32 + l) << 4)) = make_uint4(0u,0u,0u,0u);
    }
    __syncthreads();

    // ---- tile metadata ----
    int ns[TPATCH];
    int x0a[TPATCH], y0a[TPATCH], x1a[TPATCH], y1a[TPATCH];
    #pragma unroll
    for (int t = 0; t < TPATCH; t++) {
        int idx = tile*TPATCH + t;
        if (idx >= cnt) idx = cnt - 1;   // duplicate last -> identical redundant writes
        int n = g_glist[group*NPTS + idx];
        ns[t] = n;
        int ii = i_ids[n], jj = j_ids[n];
        int x0 = (ii % w0c)*2; if (x0 > WFE-1) x0 = WFE-1;
        int y0 = (ii / w0c)*2; if (y0 > HF -1) y0 = HF -1;
        int x1 = (jj % w1c)*2; if (x1 > WFE-1) x1 = WFE-1;
        int y1 = (jj / w1c)*2; if (y1 > HF -1) y1 = HF -1;
        x0a[t] = x0; y0a[t] = y0; x1a[t] = x1; y1a[t] = y1;
    }

    // ---- gather patches, tf32 round, into fragment A ----
    #pragma unroll
    for (int t = 0; t < TPATCH; t++) {
        for (int item = tid; item < 640; item += 256) {    // item = c*5 + wy
            int wy = item % 5;
            int c  = item / 5;
            float v0[5], v1[5];
            {
                int y = y0a[t] + wy - 2;
                bool yok = ((unsigned)y < (unsigned)HF);
                const float* src = f0 + ((size_t)(group*DF + c)*HF + (yok ? y : 0))*WFE;
                #pragma unroll
                for (int wx = 0; wx < 5; wx++) {
                    int x = x0a[t] + wx - 2;
                    v0[wx] = (yok && (unsigned)x < (unsigned)WFE) ? __ldg(src + x) : 0.f;
                }
            }
            {
                int y = y1a[t] + wy - 2;
                bool yok = ((unsigned)y < (unsigned)HF);
                const float* src = f1 + ((size_t)(group*DF + c)*HF + (yok ? y : 0))*WFE;
                #pragma unroll
                for (int wx = 0; wx < 5; wx++) {
                    int x = x1a[t] + wx - 2;
                    v1[wx] = (yok && (unsigned)x < (unsigned)WFE) ? __ldg(src + x) : 0.f;
                }
            }
            #pragma unroll
            for (int wx = 0; wx < 5; wx++) {
                int row = t*25 + wy*5 + wx;                // 0..49
                storeA(Abase, row, c,        v0[wx]*v1[wx]);   // cps -> k 0..127
                storeA(Abase, row, 128 + c,  v0[wx]);          // p0  -> k 128..255
                storeA(Abase, row, 256 + c,  v1[wx]);          // p1  -> k 256..383
            }
        }
    }
    __syncthreads();

    // ---- streamed B + MMA: 48 sub-panels (2 halves x 24), 8KB each ----
    float acc[2][4][4];
    #pragma unroll
    for (int i = 0; i < 2; i++)
        #pragma unroll
        for (int j = 0; j < 4; j++)
            #pragma unroll
            for (int q = 0; q < 4; q++) acc[i][j][q] = 0.f;

    uint4 pf[2];
    {
        const uint4* s0 = (const uint4*)(g_Wtf + (size_t)((0*2 + group)*12 + 0)*4096);
        #pragma unroll
        for (int i = 0; i < 2; i++) pf[i] = __ldg(s0 + i*256 + tid);
    }

    #pragma unroll 1
    for (int gp = 0; gp < 48; gp++) {
        int half = gp / 24, Pl = gp % 24;
        char* Bslot = smem + SM_B_OFF + (gp & 1)*8192;

        // store this sub-panel, prefetch next, one sync (R16-safe pattern)
        #pragma unroll
        for (int i = 0; i < 2; i++) ((uint4*)Bslot)[i*256 + tid] = pf[i];
        if (gp + 1 < 48) {
            int g2 = gp + 1, h2 = g2 / 24, P2 = g2 % 24;
            const uint4* s2 = (const uint4*)(g_Wtf
                + (size_t)((h2*2 + group)*12 + (P2 >> 1))*4096 + (P2 & 1)*2048);
            #pragma unroll
            for (int i = 0; i < 2; i++) pf[i] = __ldg(s2 + i*256 + tid);
        }
        __syncthreads();

        #pragma unroll
        for (int q = 0; q < 2; q++) {
            int kstep = Pl*2 + q;                          // A k8-step 0..47
            uint4 ua[2];
            #pragma unroll
            for (int mtl = 0; mtl < 2; mtl++)
                ua[mtl] = *(const uint4*)(Abase + (((kstep*4 + (wr*2 + mtl))*32 + lane) << 4));
            uint2 ub[4];
            #pragma unroll
            for (int ntl = 0; ntl < 4; ntl++)
                ub[ntl] = *(const uint2*)(Bslot + (((q*16 + (wc*4 + ntl))*32 + lane) << 3));
            #pragma unroll
            for (int mtl = 0; mtl < 2; mtl++)
                #pragma unroll
                for (int ntl = 0; ntl < 4; ntl++)
                    mma_tf32(acc[mtl][ntl], ua[mtl], ub[ntl]);
        }

        // ---- end of a half: write out + reset acc ----
        if (Pl == 23) {
            #pragma unroll
            for (int mtl = 0; mtl < 2; mtl++) {
                #pragma unroll
                for (int rr = 0; rr < 2; rr++) {
                    int row = wr*32 + mtl*16 + gl + rr*8;
                    if (row < TPATCH*25) {
                        int t = row / 25, pos = row % 25;
                        size_t mrow = (size_t)half*NPTS + ns[t];
                        const float* bp = g_base + mrow*128;
                        float* op = out + (mrow*25 + pos)*128;
                        #pragma unroll
                        for (int ntl = 0; ntl < 4; ntl++) {
                            int col = wc*32 + ntl*8 + tig*2;
                            float2 b = *(const float2*)(bp + col);
                            float2 v;
                            v.x = acc[mtl][ntl][rr*2 + 0] + b.x;
                            v.y = acc[mtl][ntl][rr*2 + 1] + b.y;
                            *(float2*)(op + col) = v;
                        }
                    }
                }
            }
            #pragma unroll
            for (int i = 0; i < 2; i++)
                #pragma unroll
                for (int j = 0; j < 4; j++)
                    #pragma unroll
                    for (int q = 0; q < 4; q++) acc[i][j][q] = 0.f;
        }
    }
}

// ---------------- launch ----------------
extern "C" void kernel_launch(void* const* d_in, const int* in_sizes, int n_in,
                              void* d_out, int out_size) {
    const float* f0     = (const float*)d_in[0];
    const float* f1     = (const float*)d_in[1];
    const float* fc0    = (const float*)d_in[2];
    const float* fc1    = (const float*)d_in[3];
    const float* corr_w = (const float*)d_in[4];
    const float* corr_b = (const float*)d_in[5];
    const float* dp_w   = (const float*)d_in[6];
    const float* dp_b   = (const float*)d_in[7];
    const float* mw     = (const float*)d_in[8];
    const float* mb     = (const float*)d_in[9];
    const int* b_ids    = (const int*)d_in[10];
    const int* i_ids    = (const int*)d_in[11];
    const int* j_ids    = (const int*)d_in[12];
    const int* w0c      = (const int*)d_in[13];
    const int* w1c      = (const int*)d_in[14];
    float* out          = (float*)d_out;

    (void)in_sizes; (void)n_in; (void)out_size;

    cudaFuncSetAttribute(main_kernel, cudaFuncAttributeMaxDynamicSharedMemorySize, SMEM_BYTES);

    ctx_kernel  <<<512, 256>>>(f0, f1);                                      // launch 0
    wcomb_kernel<<<641, 128>>>(corr_w, corr_b, dp_w, dp_b, mw, mb);          // launch 1
    prep_kernel <<<381, 256>>>(fc0, fc1, b_ids, i_ids, j_ids);               // launch 2
    main_kernel <<<dim3((NPTS + TPATCH - 1)/TPATCH, 2), 256, SMEM_BYTES>>>(
        f0, f1, i_ids, j_ids, w0c, w1c, out);                                // launch 3 -> ncu
}